// round 10
// baseline (speedup 1.0000x reference)
#include <cuda_runtime.h>
#include <cuda_fp16.h>
#include <math.h>
#include <stdint.h>

#define NPTS 8192
#define DIM 256
#define KC 64
#define NCHUNK (DIM / KC)
#define RPB 4
#define SM_SOFT 65536

// ---------------- static device scratch (no allocation allowed) ----------------
__device__ float  d_wc[DIM];
__device__ __half d_anh[(size_t)NPTS * DIM];
__device__ __half d_bnh[(size_t)NPTS * DIM];
__device__ __half d_Gxy[(size_t)NPTS * NPTS];
__device__ __half d_Gxx[(size_t)NPTS * NPTS];
__device__ __half d_Gyy[(size_t)NPTS * NPTS];
__device__ float  d_f[2][NPTS];
__device__ float  d_g[2][NPTS];
__device__ float  d_fxx[2][NPTS];
__device__ float  d_gyy[2][NPTS];
__device__ float  d_ffin[NPTS], d_gfin[NPTS], d_xfin[NPTS], d_yfin[NPTS];
__device__ float2 d_rowpart[64][NPTS];   // per-colTile row partials (m,s)
__device__ float2 d_colpart[8][NPTS];    // per-rowSplit col partials (m,s)

__device__ __forceinline__ float ex2f_fast(float x) {
    float y; asm("ex2.approx.ftz.f32 %0, %1;" : "=f"(y) : "f"(x)); return y;
}
__device__ __forceinline__ uint32_t smem_u32(const void* p) {
    uint32_t a;
    asm("{ .reg .u64 t; cvta.to.shared.u64 t, %1; cvt.u32.u64 %0, t; }" : "=r"(a) : "l"(p));
    return a;
}
__device__ __forceinline__ void cp_async16(uint32_t dst, const void* src) {
    asm volatile("cp.async.cg.shared.global [%0], [%1], 16;" :: "r"(dst), "l"(src) : "memory");
}
#define LDMX4(r, addr)                                                          \
    asm volatile("ldmatrix.sync.aligned.m8n8.x4.shared.b16 {%0,%1,%2,%3}, [%4];" \
                 : "=r"((r)[0]), "=r"((r)[1]), "=r"((r)[2]), "=r"((r)[3])        \
                 : "r"(addr))

// ---------------- prep ----------------
__global__ void wprep_kernel(const float* __restrict__ w) {
    __shared__ float sh[DIM];
    int t = threadIdx.x;
    float c = fminf(fmaxf(w[t], 0.0f), 2.0f);
    sh[t] = c;
    __syncthreads();
    for (int off = DIM / 2; off > 0; off >>= 1) {
        if (t < off) sh[t] += sh[t + off];
        __syncthreads();
    }
    d_wc[t] = c * ((float)DIM / sh[0]);
}

__global__ void rownorm_kernel(const float* __restrict__ x1, const float* __restrict__ x2) {
    __shared__ float sh[DIM];
    int b = blockIdx.x, t = threadIdx.x;
    float v;
    if (b < NPTS) v = d_wc[t] * x1[(size_t)b * DIM + t];
    else          v = x2[(size_t)(b - NPTS) * DIM + t];
    sh[t] = v * v;
    __syncthreads();
    for (int off = DIM / 2; off > 0; off >>= 1) {
        if (t < off) sh[t] += sh[t + off];
        __syncthreads();
    }
    float inv = 1.0f / (sqrtf(sh[0]) + 1e-12f);
    __half h = __float2half_rn(v * inv);
    if (b < NPTS) d_anh[(size_t)b * DIM + t] = h;
    else          d_bnh[(size_t)(b - NPTS) * DIM + t] = h;
}

__global__ void zero_kernel() {
    int i = blockIdx.x * blockDim.x + threadIdx.x;
    if (i < NPTS) {
        d_f[0][i] = 0.0f; d_g[0][i] = 0.0f;
        d_fxx[0][i] = 0.0f; d_gyy[0][i] = 0.0f;
    }
}

// ---------------- HMMA GEMM: C = A * B^T (+ optional transposed output CT) ----------------
__global__ void __launch_bounds__(256, 2) gemm_mma(const __half* __restrict__ A,
                                                   const __half* __restrict__ B,
                                                   __half* __restrict__ C,
                                                   __half* __restrict__ CT,
                                                   int sym) {
    extern __shared__ char smem[];
    const int btx = blockIdx.x, bty = blockIdx.y;
    if (sym && btx > bty) return;

    const uint32_t smem_base = smem_u32(smem);
    const int tid = threadIdx.x;
    const int wid = tid >> 5, lane = tid & 31;
    const int warp_m = wid >> 2, warp_n = wid & 3;
    const int rowBase = bty * 128;
    const int colBase = btx * 128;

    const int mat = lane >> 3, rin = lane & 7;
    const int a_row_in = (mat & 1) * 8 + rin;
    const int a_kh     = (mat >> 1) * 8;
    const int b_row_in = (mat >> 1) * 8 + rin;
    const int b_kh     = (mat & 1) * 8;

    float acc[4][4][4];
#pragma unroll
    for (int mi = 0; mi < 4; ++mi)
#pragma unroll
        for (int ni = 0; ni < 4; ++ni)
#pragma unroll
            for (int q = 0; q < 4; ++q) acc[mi][ni][q] = 0.0f;

#define ISSUE_CHUNK(c, b) do {                                                  \
        const __half* Asrc_ = A + (size_t)rowBase * DIM + (c) * KC;             \
        const __half* Bsrc_ = B + (size_t)colBase * DIM + (c) * KC;             \
        uint32_t Ab_ = smem_base + (b) * 32768;                                 \
        uint32_t Bb_ = Ab_ + 16384;                                             \
        _Pragma("unroll")                                                       \
        for (int q_ = 0; q_ < 4; ++q_) {                                        \
            int i_ = q_ * 256 + tid;                                            \
            int r_ = i_ >> 3, cw_ = i_ & 7;                                     \
            uint32_t off_ = r_ * 128 + (((uint32_t)(cw_ ^ (r_ & 7))) << 4);     \
            cp_async16(Ab_ + off_, Asrc_ + (size_t)r_ * DIM + cw_ * 8);         \
            cp_async16(Bb_ + off_, Bsrc_ + (size_t)r_ * DIM + cw_ * 8);         \
        }                                                                       \
        asm volatile("cp.async.commit_group;" ::: "memory");                    \
    } while (0)

    ISSUE_CHUNK(0, 0);
#pragma unroll
    for (int c = 0; c < NCHUNK; ++c) {
        if (c + 1 < NCHUNK) {
            ISSUE_CHUNK(c + 1, (c + 1) & 1);
            asm volatile("cp.async.wait_group 1;" ::: "memory");
        } else {
            asm volatile("cp.async.wait_group 0;" ::: "memory");
        }
        __syncthreads();
        uint32_t Ab = smem_base + (c & 1) * 32768;
        uint32_t Bb = Ab + 16384;
#pragma unroll
        for (int ks = 0; ks < 4; ++ks) {
            uint32_t bf[2][4];
#pragma unroll
            for (int p = 0; p < 2; ++p) {
                int nrow = warp_n * 32 + p * 16 + b_row_in;
                int kcol = ks * 16 + b_kh;
                uint32_t addr = Bb + nrow * 128 + ((uint32_t)((kcol >> 3) ^ (nrow & 7)) << 4);
                LDMX4(bf[p], addr);
            }
#pragma unroll
            for (int mi = 0; mi < 4; ++mi) {
                uint32_t af[4];
                int arow = warp_m * 64 + mi * 16 + a_row_in;
                int kcol = ks * 16 + a_kh;
                uint32_t addr = Ab + arow * 128 + ((uint32_t)((kcol >> 3) ^ (arow & 7)) << 4);
                LDMX4(af, addr);
#pragma unroll
                for (int ni = 0; ni < 4; ++ni) {
                    asm volatile(
                        "mma.sync.aligned.m16n8k16.row.col.f32.f16.f16.f32 "
                        "{%0,%1,%2,%3}, {%4,%5,%6,%7}, {%8,%9}, {%0,%1,%2,%3};"
                        : "+f"(acc[mi][ni][0]), "+f"(acc[mi][ni][1]),
                          "+f"(acc[mi][ni][2]), "+f"(acc[mi][ni][3])
                        : "r"(af[0]), "r"(af[1]), "r"(af[2]), "r"(af[3]),
                          "r"(bf[ni >> 1][(ni & 1) * 2]), "r"(bf[ni >> 1][(ni & 1) * 2 + 1]));
                }
            }
        }
        __syncthreads();
    }
#undef ISSUE_CHUNK

    __half* stage = (__half*)smem;
#pragma unroll
    for (int mi = 0; mi < 4; ++mi)
#pragma unroll
        for (int ni = 0; ni < 4; ++ni) {
            int row = warp_m * 64 + mi * 16 + (lane >> 2);
            int col = warp_n * 32 + ni * 8 + 2 * (lane & 3);
            __half2 lo = __floats2half2_rn(acc[mi][ni][0], acc[mi][ni][1]);
            __half2 hi = __floats2half2_rn(acc[mi][ni][2], acc[mi][ni][3]);
            *(__half2*)(stage + row * 136 + col)       = lo;
            *(__half2*)(stage + (row + 8) * 136 + col) = hi;
        }
    __syncthreads();
#pragma unroll
    for (int i = tid; i < 2048; i += 256) {
        int r = i >> 4, ch = i & 15;
        uint4 v = *(uint4*)(stage + r * 136 + ch * 8);
        *(uint4*)(C + (size_t)(rowBase + r) * NPTS + colBase + ch * 8) = v;
    }

    if (CT != nullptr && !(sym && btx == bty)) {
        __syncthreads();
#pragma unroll
        for (int mi = 0; mi < 4; ++mi)
#pragma unroll
            for (int ni = 0; ni < 4; ++ni) {
                int row = warp_m * 64 + mi * 16 + (lane >> 2);
                int col = warp_n * 32 + ni * 8 + 2 * (lane & 3);
                stage[col * 136 + row]           = __float2half_rn(acc[mi][ni][0]);
                stage[(col + 1) * 136 + row]     = __float2half_rn(acc[mi][ni][1]);
                stage[col * 136 + row + 8]       = __float2half_rn(acc[mi][ni][2]);
                stage[(col + 1) * 136 + row + 8] = __float2half_rn(acc[mi][ni][3]);
            }
        __syncthreads();
#pragma unroll
        for (int i = tid; i < 2048; i += 256) {
            int r = i >> 4, ch = i & 15;
            uint4 v = *(uint4*)(stage + r * 136 + ch * 8);
            *(uint4*)(CT + (size_t)(colBase + r) * NPTS + rowBase + ch * 8) = v;
        }
    }
}

// ---------------- fused Sinkhorn iteration kernel ----------------
// blockIdx.y == 0 : cross tile pass over Gxy (bx < 512): emits row partials
//                   (for f, pot=g) and col partials (for g, pot=f).
// blockIdx.y == 1 : Gxx row softmin (fxx)   -- R7-proven path
// blockIdx.y == 2 : Gyy row softmin (gyy)
struct KAArgs {
    const float* potxx; const float* oldxx; float* outxx; int avgxx;
    const float* potyy; const float* oldyy; float* outyy; int avgyy;
    const float* fcur;  const float* gcur;
};

__global__ void __launch_bounds__(256) sinkhorn_iter(KAArgs args, float eps) {
    extern __shared__ char smg[];
    const uint32_t smg_u = smem_u32(smg);
    const int var = blockIdx.y;
    const int tid = threadIdx.x;
    const int lane = tid & 31, wid = tid >> 5;

    const float L2E = 1.4426950408889634f;
    const float c1 = L2E / eps;
    const float c0 = -c1;

    if (var == 0) {
        // ---------- cross tile pass ----------
        const int bx = blockIdx.x;
        if (bx >= 512) return;
        const int colTile = bx & 63, rowSplit = bx >> 6;
        const int colGrp = tid & 15, rowOff = tid >> 4;
        const int colBase = colTile * 128 + colGrp * 8;

        float gg[8];
#pragma unroll
        for (int k = 0; k < 8; ++k)
            gg[k] = fmaf(__ldg(args.gcur + colBase + k), c1, c0);

        float cm[8], cs[8];
#pragma unroll
        for (int k = 0; k < 8; ++k) { cm[k] = -INFINITY; cs[k] = 0.0f; }

        const int rbase = rowSplit * 1024 + rowOff;
#pragma unroll 2
        for (int s = 0; s < 64; ++s) {
            int row = rbase + s * 16;
            uint4 q = *(const uint4*)(d_Gxy + (size_t)row * NPTS + colBase);
            float fv = fmaf(__ldg(args.fcur + row), c1, c0);
            float2 h0 = __half22float2(*(const __half2*)&q.x);
            float2 h1 = __half22float2(*(const __half2*)&q.y);
            float2 h2 = __half22float2(*(const __half2*)&q.z);
            float2 h3 = __half22float2(*(const __half2*)&q.w);
            float e[8];
            e[0] = h0.x * c1; e[1] = h0.y * c1;
            e[2] = h1.x * c1; e[3] = h1.y * c1;
            e[4] = h2.x * c1; e[5] = h2.y * c1;
            e[6] = h3.x * c1; e[7] = h3.y * c1;

            // row-LSE partial (for f): pot = g
            float uf[8];
#pragma unroll
            for (int k = 0; k < 8; ++k) uf[k] = e[k] + gg[k];
            float m8 = fmaxf(fmaxf(fmaxf(uf[0], uf[1]), fmaxf(uf[2], uf[3])),
                             fmaxf(fmaxf(uf[4], uf[5]), fmaxf(uf[6], uf[7])));
#pragma unroll
            for (int off = 1; off < 16; off <<= 1)
                m8 = fmaxf(m8, __shfl_xor_sync(0xffffffffu, m8, off));
            float se = 0.0f;
#pragma unroll
            for (int k = 0; k < 8; ++k) se += ex2f_fast(uf[k] - m8);
#pragma unroll
            for (int off = 1; off < 16; off <<= 1)
                se += __shfl_xor_sync(0xffffffffu, se, off);
            if (colGrp == 0) d_rowpart[colTile][row] = make_float2(m8, se);

            // col online LSE (for g): pot = f
#pragma unroll
            for (int k = 0; k < 8; ++k) {
                float v = e[k] + fv;
                if (v <= cm[k]) {
                    cs[k] += ex2f_fast(v - cm[k]);
                } else {
                    cs[k] = fmaf(cs[k], ex2f_fast(cm[k] - v), 1.0f);
                    cm[k] = v;
                }
            }
        }

        // merge col partials across the 16 rowOff threads per column
        float2* smp = (float2*)smg;     // [256][8]
#pragma unroll
        for (int k = 0; k < 8; ++k) smp[tid * 8 + k] = make_float2(cm[k], cs[k]);
        __syncthreads();
        if (tid < 128) {
            int col = tid, cg = col >> 3, k = col & 7;
            float m = -INFINITY, s = 0.0f;
#pragma unroll
            for (int r = 0; r < 16; ++r) {
                float2 p = smp[(r * 16 + cg) * 8 + k];
                float mm = fmaxf(m, p.x);
                s = s * ex2f_fast(m - mm) + p.y * ex2f_fast(p.x - mm);
                m = mm;
            }
            d_colpart[rowSplit][colTile * 128 + col] = make_float2(m, s);
        }
        return;
    }

    // ---------- dense row softmin (Gxx / Gyy), R7-proven path ----------
    const __half* Gbase = (var == 1) ? d_Gxx : d_Gyy;
    const float*  pot   = (var == 1) ? args.potxx : args.potyy;
    const float*  oldp  = (var == 1) ? args.oldxx : args.oldyy;
    float*        out   = (var == 1) ? args.outxx : args.outyy;
    const int     avg   = (var == 1) ? args.avgxx : args.avgyy;
    const int     row0  = blockIdx.x * RPB;

#pragma unroll
    for (int r = 0; r < RPB; ++r) {
        const __half* Gr = Gbase + (size_t)(row0 + r) * NPTS;
#pragma unroll
        for (int q = 0; q < 4; ++q) {
            int idx = q * 256 + tid;
            cp_async16(smg_u + r * 16384 + idx * 16, Gr + idx * 8);
        }
    }
    asm volatile("cp.async.commit_group;" ::: "memory");

    float pp[32];
#pragma unroll
    for (int it = 0; it < 4; ++it) {
        int idx = it * 256 + tid;
        float4 a = ((const float4*)pot)[2 * idx];
        float4 b = ((const float4*)pot)[2 * idx + 1];
        pp[8 * it + 0] = fmaf(a.x, c1, c0); pp[8 * it + 1] = fmaf(a.y, c1, c0);
        pp[8 * it + 2] = fmaf(a.z, c1, c0); pp[8 * it + 3] = fmaf(a.w, c1, c0);
        pp[8 * it + 4] = fmaf(b.x, c1, c0); pp[8 * it + 5] = fmaf(b.y, c1, c0);
        pp[8 * it + 6] = fmaf(b.z, c1, c0); pp[8 * it + 7] = fmaf(b.w, c1, c0);
    }

    asm volatile("cp.async.wait_group 0;" ::: "memory");

    __shared__ float sA[RPB][8];
    __shared__ float sS[RPB][8];

    float wtm[RPB];
#pragma unroll
    for (int r = 0; r < RPB; ++r) {
        float tm = -INFINITY;
#pragma unroll
        for (int it = 0; it < 4; ++it) {
            uint4 q = *(const uint4*)(smg + r * 16384 + (it * 256 + tid) * 16);
            float2 g0 = __half22float2(*(const __half2*)&q.x);
            float2 g1 = __half22float2(*(const __half2*)&q.y);
            float2 g2 = __half22float2(*(const __half2*)&q.z);
            float2 g3 = __half22float2(*(const __half2*)&q.w);
            float v0 = fmaf(g0.x, c1, pp[8 * it + 0]);
            float v1 = fmaf(g0.y, c1, pp[8 * it + 1]);
            float v2 = fmaf(g1.x, c1, pp[8 * it + 2]);
            float v3 = fmaf(g1.y, c1, pp[8 * it + 3]);
            float v4 = fmaf(g2.x, c1, pp[8 * it + 4]);
            float v5 = fmaf(g2.y, c1, pp[8 * it + 5]);
            float v6 = fmaf(g3.x, c1, pp[8 * it + 6]);
            float v7 = fmaf(g3.y, c1, pp[8 * it + 7]);
            tm = fmaxf(tm, fmaxf(fmaxf(fmaxf(v0, v1), fmaxf(v2, v3)),
                                 fmaxf(fmaxf(v4, v5), fmaxf(v6, v7))));
        }
#pragma unroll
        for (int off = 16; off > 0; off >>= 1)
            tm = fmaxf(tm, __shfl_xor_sync(0xffffffffu, tm, off));
        wtm[r] = tm;
        if (lane == 0) sA[r][wid] = tm;
    }
    __syncthreads();
    float M[RPB];
#pragma unroll
    for (int r = 0; r < RPB; ++r) {
        float m = sA[r][0];
#pragma unroll
        for (int i = 1; i < 8; ++i) m = fmaxf(m, sA[r][i]);
        M[r] = m;
    }

#pragma unroll
    for (int r = 0; r < RPB; ++r) {
        float s = 0.0f;
        if (wtm[r] >= M[r] - 40.0f) {
            float Mr = M[r];
            float s0 = 0.f, s1 = 0.f, s2 = 0.f, s3 = 0.f;
#pragma unroll
            for (int it = 0; it < 4; ++it) {
                uint4 q = *(const uint4*)(smg + r * 16384 + (it * 256 + tid) * 16);
                float2 g0 = __half22float2(*(const __half2*)&q.x);
                float2 g1 = __half22float2(*(const __half2*)&q.y);
                float2 g2 = __half22float2(*(const __half2*)&q.z);
                float2 g3 = __half22float2(*(const __half2*)&q.w);
                s0 += ex2f_fast(fmaf(g0.x, c1, pp[8 * it + 0]) - Mr);
                s1 += ex2f_fast(fmaf(g0.y, c1, pp[8 * it + 1]) - Mr);
                s2 += ex2f_fast(fmaf(g1.x, c1, pp[8 * it + 2]) - Mr);
                s3 += ex2f_fast(fmaf(g1.y, c1, pp[8 * it + 3]) - Mr);
                s0 += ex2f_fast(fmaf(g2.x, c1, pp[8 * it + 4]) - Mr);
                s1 += ex2f_fast(fmaf(g2.y, c1, pp[8 * it + 5]) - Mr);
                s2 += ex2f_fast(fmaf(g3.x, c1, pp[8 * it + 6]) - Mr);
                s3 += ex2f_fast(fmaf(g3.y, c1, pp[8 * it + 7]) - Mr);
            }
            s = (s0 + s1) + (s2 + s3);
        }
#pragma unroll
        for (int off = 16; off > 0; off >>= 1)
            s += __shfl_xor_sync(0xffffffffu, s, off);
        if (lane == 0) sS[r][wid] = s;
    }
    __syncthreads();

    if (tid < RPB) {
        int r = tid;
        float S = ((sS[r][0] + sS[r][1]) + (sS[r][2] + sS[r][3]))
                + ((sS[r][4] + sS[r][5]) + (sS[r][6] + sS[r][7]));
        const float LOGW = -9.010913347279288f;   // -log(8192)
        const float LN2  = 0.6931471805599453f;
        float lse = (M[r] + log2f(S)) * LN2;
        float res = -eps * (LOGW + lse);
        if (avg) res = 0.5f * (oldp[row0 + r] + res);
        out[row0 + r] = res;
    }
}

// ---------------- partial merge: finalize f (64 partials) and g (8 partials) ----------------
__global__ void merge_kernel(float* __restrict__ outf, float* __restrict__ outg, float eps) {
    const int i = blockIdx.x * 256 + threadIdx.x;
    const float LOGW = -9.010913347279288f;
    const float LN2  = 0.6931471805599453f;
    if (i < NPTS) {
        float m = -INFINITY, s = 0.0f;
#pragma unroll 8
        for (int t = 0; t < 64; ++t) {
            float2 p = d_rowpart[t][i];
            float mm = fmaxf(m, p.x);
            s = s * ex2f_fast(m - mm) + p.y * ex2f_fast(p.x - mm);
            m = mm;
        }
        outf[i] = -eps * (LOGW + (m + log2f(s)) * LN2);
    } else {
        int col = i - NPTS;
        float m = -INFINITY, s = 0.0f;
#pragma unroll
        for (int t = 0; t < 8; ++t) {
            float2 p = d_colpart[t][col];
            float mm = fmaxf(m, p.x);
            s = s * ex2f_fast(m - mm) + p.y * ex2f_fast(p.x - mm);
            m = mm;
        }
        outg[col] = -eps * (LOGW + (m + log2f(s)) * LN2);
    }
}

// ---------------- final reduction ----------------
__global__ void final_reduce(float* __restrict__ out) {
    __shared__ float sh[1024];
    int t = threadIdx.x;
    float s = 0.0f;
    for (int i = t; i < NPTS; i += 1024)
        s += (d_ffin[i] - d_xfin[i]) + (d_gfin[i] - d_yfin[i]);
    sh[t] = s;
    __syncthreads();
    for (int off = 512; off > 0; off >>= 1) {
        if (t < off) sh[t] += sh[t + off];
        __syncthreads();
    }
    if (t == 0) out[0] = sh[0] / (float)NPTS;
}

// ---------------- host ----------------
static void* symaddr(const void* sym) {
    void* p = nullptr;
    cudaGetSymbolAddress(&p, sym);
    return p;
}

#define GEMM_SMEM 65536

extern "C" void kernel_launch(void* const* d_in, const int* in_sizes, int n_in,
                              void* d_out, int out_size) {
    const float* x1 = (const float*)d_in[0];
    const float* x2 = (const float*)d_in[1];
    const float* w  = (const float*)d_in[2];

    __half* an  = (__half*)symaddr(d_anh);
    __half* bn  = (__half*)symaddr(d_bnh);
    __half* Gxy = (__half*)symaddr(d_Gxy);
    __half* Gxx = (__half*)symaddr(d_Gxx);
    __half* Gyy = (__half*)symaddr(d_Gyy);
    float* fb  = (float*)symaddr(d_f);
    float* gb  = (float*)symaddr(d_g);
    float* xb  = (float*)symaddr(d_fxx);
    float* yb  = (float*)symaddr(d_gyy);
    float* ffin = (float*)symaddr(d_ffin);
    float* gfin = (float*)symaddr(d_gfin);
    float* xfin = (float*)symaddr(d_xfin);
    float* yfin = (float*)symaddr(d_yfin);

    cudaFuncSetAttribute(gemm_mma, cudaFuncAttributeMaxDynamicSharedMemorySize, GEMM_SMEM);
    cudaFuncSetAttribute(sinkhorn_iter, cudaFuncAttributeMaxDynamicSharedMemorySize, SM_SOFT);

    wprep_kernel<<<1, DIM>>>(w);
    rownorm_kernel<<<2 * NPTS, DIM>>>(x1, x2);
    zero_kernel<<<NPTS / 256, 256>>>();

    dim3 ggrid(NPTS / 128, NPTS / 128);
    gemm_mma<<<ggrid, 256, GEMM_SMEM>>>(an, bn, Gxy, nullptr, 0);
    gemm_mma<<<ggrid, 256, GEMM_SMEM>>>(an, an, Gxx, Gxx, 1);
    gemm_mma<<<ggrid, 256, GEMM_SMEM>>>(bn, bn, Gyy, Gyy, 1);

    const float eps_list[10] = {4.0f, 1.0f, 0.25f, 0.0625f, 0.015625f,
                                0.00390625f, 0.0025f, 0.0025f, 0.0025f, 0.0025f};
    dim3 sgrid(NPTS / RPB, 3);
    int cur = 0;
    for (int i = 0; i < 10; ++i) {
        float eps = eps_list[i];
        int nxt = 1 - cur;
        KAArgs a;
        a.potxx = xb + cur * NPTS; a.oldxx = xb + cur * NPTS; a.outxx = xb + nxt * NPTS; a.avgxx = 1;
        a.potyy = yb + cur * NPTS; a.oldyy = yb + cur * NPTS; a.outyy = yb + nxt * NPTS; a.avgyy = 1;
        a.fcur = fb + cur * NPTS; a.gcur = gb + cur * NPTS;
        sinkhorn_iter<<<sgrid, 256, SM_SOFT>>>(a, eps);
        merge_kernel<<<2 * NPTS / 256, 256>>>(fb + nxt * NPTS, gb + nxt * NPTS, eps);
        cur = nxt;
    }

    const float epsF = 0.0025f;
    {
        KAArgs a;
        a.potxx = xb + cur * NPTS; a.oldxx = nullptr; a.outxx = xfin; a.avgxx = 0;
        a.potyy = yb + cur * NPTS; a.oldyy = nullptr; a.outyy = yfin; a.avgyy = 0;
        a.fcur = fb + cur * NPTS; a.gcur = gb + cur * NPTS;
        sinkhorn_iter<<<sgrid, 256, SM_SOFT>>>(a, epsF);
        merge_kernel<<<2 * NPTS / 256, 256>>>(ffin, gfin, epsF);
    }

    final_reduce<<<1, 1024>>>((float*)d_out);
}

// round 11
// speedup vs baseline: 1.1653x; 1.1653x over previous
#include <cuda_runtime.h>
#include <cuda_fp16.h>
#include <math.h>
#include <stdint.h>

#define NPTS 8192
#define DIM 256
#define KC 64
#define NCHUNK (DIM / KC)
#define RPBLK 16                 // rows per softmin block
#define BATCH 2                  // rows per pipeline batch (32 KB)
#define NBATCH (RPBLK / BATCH)   // 8
#define SM_SOFTMIN 65536         // 2 ping-pong buffers x 32 KB

// ---------------- static device scratch (no allocation allowed) ----------------
__device__ float  d_wc[DIM];
__device__ __half d_anh[(size_t)NPTS * DIM];
__device__ __half d_bnh[(size_t)NPTS * DIM];
__device__ __half d_Gxy[(size_t)NPTS * NPTS];
__device__ __half d_Gyx[(size_t)NPTS * NPTS];
__device__ __half d_Gxx[(size_t)NPTS * NPTS];
__device__ __half d_Gyy[(size_t)NPTS * NPTS];
__device__ float  d_f[2][NPTS];
__device__ float  d_g[2][NPTS];
__device__ float  d_fxx[2][NPTS];
__device__ float  d_gyy[2][NPTS];
__device__ float  d_ffin[NPTS], d_gfin[NPTS], d_xfin[NPTS], d_yfin[NPTS];

__device__ __forceinline__ float ex2f_fast(float x) {
    float y; asm("ex2.approx.ftz.f32 %0, %1;" : "=f"(y) : "f"(x)); return y;
}
__device__ __forceinline__ uint32_t smem_u32(const void* p) {
    uint32_t a;
    asm("{ .reg .u64 t; cvta.to.shared.u64 t, %1; cvt.u32.u64 %0, t; }" : "=r"(a) : "l"(p));
    return a;
}
__device__ __forceinline__ void cp_async16(uint32_t dst, const void* src) {
    asm volatile("cp.async.cg.shared.global [%0], [%1], 16;" :: "r"(dst), "l"(src) : "memory");
}
#define LDMX4(r, addr)                                                          \
    asm volatile("ldmatrix.sync.aligned.m8n8.x4.shared.b16 {%0,%1,%2,%3}, [%4];" \
                 : "=r"((r)[0]), "=r"((r)[1]), "=r"((r)[2]), "=r"((r)[3])        \
                 : "r"(addr))

// ---------------- prep ----------------
__global__ void wprep_kernel(const float* __restrict__ w) {
    __shared__ float sh[DIM];
    int t = threadIdx.x;
    float c = fminf(fmaxf(w[t], 0.0f), 2.0f);
    sh[t] = c;
    __syncthreads();
    for (int off = DIM / 2; off > 0; off >>= 1) {
        if (t < off) sh[t] += sh[t + off];
        __syncthreads();
    }
    d_wc[t] = c * ((float)DIM / sh[0]);
}

__global__ void rownorm_kernel(const float* __restrict__ x1, const float* __restrict__ x2) {
    __shared__ float sh[DIM];
    int b = blockIdx.x, t = threadIdx.x;
    float v;
    if (b < NPTS) v = d_wc[t] * x1[(size_t)b * DIM + t];
    else          v = x2[(size_t)(b - NPTS) * DIM + t];
    sh[t] = v * v;
    __syncthreads();
    for (int off = DIM / 2; off > 0; off >>= 1) {
        if (t < off) sh[t] += sh[t + off];
        __syncthreads();
    }
    float inv = 1.0f / (sqrtf(sh[0]) + 1e-12f);
    __half h = __float2half_rn(v * inv);
    if (b < NPTS) d_anh[(size_t)b * DIM + t] = h;
    else          d_bnh[(size_t)(b - NPTS) * DIM + t] = h;
}

__global__ void zero_kernel() {
    int i = blockIdx.x * blockDim.x + threadIdx.x;
    if (i < NPTS) {
        d_f[0][i] = 0.0f; d_g[0][i] = 0.0f;
        d_fxx[0][i] = 0.0f; d_gyy[0][i] = 0.0f;
    }
}

// ---------------- HMMA GEMM: C = A * B^T (+ transposed output CT) ----------------
__global__ void __launch_bounds__(256, 2) gemm_mma(const __half* __restrict__ A,
                                                   const __half* __restrict__ B,
                                                   __half* __restrict__ C,
                                                   __half* __restrict__ CT,
                                                   int sym) {
    extern __shared__ char smem[];
    const int btx = blockIdx.x, bty = blockIdx.y;
    if (sym && btx > bty) return;

    const uint32_t smem_base = smem_u32(smem);
    const int tid = threadIdx.x;
    const int wid = tid >> 5, lane = tid & 31;
    const int warp_m = wid >> 2, warp_n = wid & 3;
    const int rowBase = bty * 128;
    const int colBase = btx * 128;

    const int mat = lane >> 3, rin = lane & 7;
    const int a_row_in = (mat & 1) * 8 + rin;
    const int a_kh     = (mat >> 1) * 8;
    const int b_row_in = (mat >> 1) * 8 + rin;
    const int b_kh     = (mat & 1) * 8;

    float acc[4][4][4];
#pragma unroll
    for (int mi = 0; mi < 4; ++mi)
#pragma unroll
        for (int ni = 0; ni < 4; ++ni)
#pragma unroll
            for (int q = 0; q < 4; ++q) acc[mi][ni][q] = 0.0f;

#define ISSUE_CHUNK(c, b) do {                                                  \
        const __half* Asrc_ = A + (size_t)rowBase * DIM + (c) * KC;             \
        const __half* Bsrc_ = B + (size_t)colBase * DIM + (c) * KC;             \
        uint32_t Ab_ = smem_base + (b) * 32768;                                 \
        uint32_t Bb_ = Ab_ + 16384;                                             \
        _Pragma("unroll")                                                       \
        for (int q_ = 0; q_ < 4; ++q_) {                                        \
            int i_ = q_ * 256 + tid;                                            \
            int r_ = i_ >> 3, cw_ = i_ & 7;                                     \
            uint32_t off_ = r_ * 128 + (((uint32_t)(cw_ ^ (r_ & 7))) << 4);     \
            cp_async16(Ab_ + off_, Asrc_ + (size_t)r_ * DIM + cw_ * 8);         \
            cp_async16(Bb_ + off_, Bsrc_ + (size_t)r_ * DIM + cw_ * 8);         \
        }                                                                       \
        asm volatile("cp.async.commit_group;" ::: "memory");                    \
    } while (0)

    ISSUE_CHUNK(0, 0);
#pragma unroll
    for (int c = 0; c < NCHUNK; ++c) {
        if (c + 1 < NCHUNK) {
            ISSUE_CHUNK(c + 1, (c + 1) & 1);
            asm volatile("cp.async.wait_group 1;" ::: "memory");
        } else {
            asm volatile("cp.async.wait_group 0;" ::: "memory");
        }
        __syncthreads();
        uint32_t Ab = smem_base + (c & 1) * 32768;
        uint32_t Bb = Ab + 16384;
#pragma unroll
        for (int ks = 0; ks < 4; ++ks) {
            uint32_t bf[2][4];
#pragma unroll
            for (int p = 0; p < 2; ++p) {
                int nrow = warp_n * 32 + p * 16 + b_row_in;
                int kcol = ks * 16 + b_kh;
                uint32_t addr = Bb + nrow * 128 + ((uint32_t)((kcol >> 3) ^ (nrow & 7)) << 4);
                LDMX4(bf[p], addr);
            }
#pragma unroll
            for (int mi = 0; mi < 4; ++mi) {
                uint32_t af[4];
                int arow = warp_m * 64 + mi * 16 + a_row_in;
                int kcol = ks * 16 + a_kh;
                uint32_t addr = Ab + arow * 128 + ((uint32_t)((kcol >> 3) ^ (arow & 7)) << 4);
                LDMX4(af, addr);
#pragma unroll
                for (int ni = 0; ni < 4; ++ni) {
                    asm volatile(
                        "mma.sync.aligned.m16n8k16.row.col.f32.f16.f16.f32 "
                        "{%0,%1,%2,%3}, {%4,%5,%6,%7}, {%8,%9}, {%0,%1,%2,%3};"
                        : "+f"(acc[mi][ni][0]), "+f"(acc[mi][ni][1]),
                          "+f"(acc[mi][ni][2]), "+f"(acc[mi][ni][3])
                        : "r"(af[0]), "r"(af[1]), "r"(af[2]), "r"(af[3]),
                          "r"(bf[ni >> 1][(ni & 1) * 2]), "r"(bf[ni >> 1][(ni & 1) * 2 + 1]));
                }
            }
        }
        __syncthreads();
    }
#undef ISSUE_CHUNK

    __half* stage = (__half*)smem;
#pragma unroll
    for (int mi = 0; mi < 4; ++mi)
#pragma unroll
        for (int ni = 0; ni < 4; ++ni) {
            int row = warp_m * 64 + mi * 16 + (lane >> 2);
            int col = warp_n * 32 + ni * 8 + 2 * (lane & 3);
            __half2 lo = __floats2half2_rn(acc[mi][ni][0], acc[mi][ni][1]);
            __half2 hi = __floats2half2_rn(acc[mi][ni][2], acc[mi][ni][3]);
            *(__half2*)(stage + row * 136 + col)       = lo;
            *(__half2*)(stage + (row + 8) * 136 + col) = hi;
        }
    __syncthreads();
#pragma unroll
    for (int i = tid; i < 2048; i += 256) {
        int r = i >> 4, ch = i & 15;
        uint4 v = *(uint4*)(stage + r * 136 + ch * 8);
        *(uint4*)(C + (size_t)(rowBase + r) * NPTS + colBase + ch * 8) = v;
    }

    if (!(sym && btx == bty)) {
        __syncthreads();
#pragma unroll
        for (int mi = 0; mi < 4; ++mi)
#pragma unroll
            for (int ni = 0; ni < 4; ++ni) {
                int row = warp_m * 64 + mi * 16 + (lane >> 2);
                int col = warp_n * 32 + ni * 8 + 2 * (lane & 3);
                stage[col * 136 + row]           = __float2half_rn(acc[mi][ni][0]);
                stage[(col + 1) * 136 + row]     = __float2half_rn(acc[mi][ni][1]);
                stage[col * 136 + row + 8]       = __float2half_rn(acc[mi][ni][2]);
                stage[(col + 1) * 136 + row + 8] = __float2half_rn(acc[mi][ni][3]);
            }
        __syncthreads();
#pragma unroll
        for (int i = tid; i < 2048; i += 256) {
            int r = i >> 4, ch = i & 15;
            uint4 v = *(uint4*)(stage + r * 136 + ch * 8);
            *(uint4*)(CT + (size_t)(colBase + r) * NPTS + rowBase + ch * 8) = v;
        }
    }
}

// ---------------- dense softmin: double-buffered 2-row batches, 16 rows/block ----------------
struct SMArgs {
    const __half* G[4];
    const float*  pot[4];
    const float*  oldpot[4];
    float*        out[4];
    int           avg[4];
};

// issue one 2-row batch (32 KB) into buffer buf (0/1); 8 x 16B per thread
#define SM_ISSUE_BATCH(bb, buf) do {                                            \
        const __half* Gr0_ = Gbase + (size_t)(row0 + (bb) * BATCH) * NPTS;      \
        uint32_t base_ = smg_u + (buf) * 32768;                                 \
        _Pragma("unroll")                                                       \
        for (int q_ = 0; q_ < 8; ++q_) {                                        \
            int idx_ = q_ * 256 + tid;    /* 0..2047 16B chunks over 2 rows */  \
            cp_async16(base_ + idx_ * 16, Gr0_ + idx_ * 8);                     \
        }                                                                       \
        asm volatile("cp.async.commit_group;" ::: "memory");                    \
    } while (0)

__global__ void __launch_bounds__(256) softmin4(SMArgs args, float eps) {
    extern __shared__ char smg[];               // 2 x 32 KB ping-pong
    const uint32_t smg_u = smem_u32(smg);
    const int var  = blockIdx.y;
    const int row0 = blockIdx.x * RPBLK;
    const int tid  = threadIdx.x;
    const int lane = tid & 31, wid = tid >> 5;

    const float L2E = 1.4426950408889634f;
    const float c1 = L2E / eps;
    const float c0 = -c1;

    const __half* Gbase = args.G[var];

    // prime the pipeline: batches 0 and 1 in flight
    SM_ISSUE_BATCH(0, 0);
    SM_ISSUE_BATCH(1, 1);

    // fold pot while copies fly: pp[k] = (pot_k - 1) * c1
    const float* pot = args.pot[var];
    float pp[32];
#pragma unroll
    for (int it = 0; it < 4; ++it) {
        int idx = it * 256 + tid;
        float4 a = ((const float4*)pot)[2 * idx];
        float4 b = ((const float4*)pot)[2 * idx + 1];
        pp[8 * it + 0] = fmaf(a.x, c1, c0); pp[8 * it + 1] = fmaf(a.y, c1, c0);
        pp[8 * it + 2] = fmaf(a.z, c1, c0); pp[8 * it + 3] = fmaf(a.w, c1, c0);
        pp[8 * it + 4] = fmaf(b.x, c1, c0); pp[8 * it + 5] = fmaf(b.y, c1, c0);
        pp[8 * it + 6] = fmaf(b.z, c1, c0); pp[8 * it + 7] = fmaf(b.w, c1, c0);
    }

    __shared__ float sA[BATCH][8];
    __shared__ float sS[BATCH][8];
    const float LOGW = -9.010913347279288f;   // -log(8192)
    const float LN2  = 0.6931471805599453f;

    for (int b = 0; b < NBATCH; ++b) {
        const int buf = b & 1;
        // wait until batch b's data is in smem (<=1 newer group still pending)
        if (b + 2 <= NBATCH - 1 || b == NBATCH - 2)
            asm volatile("cp.async.wait_group 1;" ::: "memory");
        else if (b == NBATCH - 1)
            asm volatile("cp.async.wait_group 0;" ::: "memory");
        else
            asm volatile("cp.async.wait_group 1;" ::: "memory");

        const char* bufp = smg + buf * 32768;

        // ---- pass A: per-row max ----
        float wtm[BATCH];
#pragma unroll
        for (int r = 0; r < BATCH; ++r) {
            float tm = -INFINITY;
#pragma unroll
            for (int it = 0; it < 4; ++it) {
                uint4 q = *(const uint4*)(bufp + r * 16384 + (it * 256 + tid) * 16);
                float2 g0 = __half22float2(*(const __half2*)&q.x);
                float2 g1 = __half22float2(*(const __half2*)&q.y);
                float2 g2 = __half22float2(*(const __half2*)&q.z);
                float2 g3 = __half22float2(*(const __half2*)&q.w);
                float v0 = fmaf(g0.x, c1, pp[8 * it + 0]);
                float v1 = fmaf(g0.y, c1, pp[8 * it + 1]);
                float v2 = fmaf(g1.x, c1, pp[8 * it + 2]);
                float v3 = fmaf(g1.y, c1, pp[8 * it + 3]);
                float v4 = fmaf(g2.x, c1, pp[8 * it + 4]);
                float v5 = fmaf(g2.y, c1, pp[8 * it + 5]);
                float v6 = fmaf(g3.x, c1, pp[8 * it + 6]);
                float v7 = fmaf(g3.y, c1, pp[8 * it + 7]);
                tm = fmaxf(tm, fmaxf(fmaxf(fmaxf(v0, v1), fmaxf(v2, v3)),
                                     fmaxf(fmaxf(v4, v5), fmaxf(v6, v7))));
            }
#pragma unroll
            for (int off = 16; off > 0; off >>= 1)
                tm = fmaxf(tm, __shfl_xor_sync(0xffffffffu, tm, off));
            wtm[r] = tm;
            if (lane == 0) sA[r][wid] = tm;
        }
        __syncthreads();
        float M[BATCH];
#pragma unroll
        for (int r = 0; r < BATCH; ++r) {
            float m = sA[r][0];
#pragma unroll
            for (int i = 1; i < 8; ++i) m = fmaxf(m, sA[r][i]);
            M[r] = m;
        }

        // ---- pass B: exp-sum, contributing warps only ----
#pragma unroll
        for (int r = 0; r < BATCH; ++r) {
            float s = 0.0f;
            if (wtm[r] >= M[r] - 40.0f) {
                float Mr = M[r];
                float s0 = 0.f, s1 = 0.f, s2 = 0.f, s3 = 0.f;
#pragma unroll
                for (int it = 0; it < 4; ++it) {
                    uint4 q = *(const uint4*)(bufp + r * 16384 + (it * 256 + tid) * 16);
                    float2 g0 = __half22float2(*(const __half2*)&q.x);
                    float2 g1 = __half22float2(*(const __half2*)&q.y);
                    float2 g2 = __half22float2(*(const __half2*)&q.z);
                    float2 g3 = __half22float2(*(const __half2*)&q.w);
                    s0 += ex2f_fast(fmaf(g0.x, c1, pp[8 * it + 0]) - Mr);
                    s1 += ex2f_fast(fmaf(g0.y, c1, pp[8 * it + 1]) - Mr);
                    s2 += ex2f_fast(fmaf(g1.x, c1, pp[8 * it + 2]) - Mr);
                    s3 += ex2f_fast(fmaf(g1.y, c1, pp[8 * it + 3]) - Mr);
                    s0 += ex2f_fast(fmaf(g2.x, c1, pp[8 * it + 4]) - Mr);
                    s1 += ex2f_fast(fmaf(g2.y, c1, pp[8 * it + 5]) - Mr);
                    s2 += ex2f_fast(fmaf(g3.x, c1, pp[8 * it + 6]) - Mr);
                    s3 += ex2f_fast(fmaf(g3.y, c1, pp[8 * it + 7]) - Mr);
                }
                s = (s0 + s1) + (s2 + s3);
            }
#pragma unroll
            for (int off = 16; off > 0; off >>= 1)
                s += __shfl_xor_sync(0xffffffffu, s, off);
            if (lane == 0) sS[r][wid] = s;
        }
        __syncthreads();

        if (tid < BATCH) {
            int r = tid;
            int row = row0 + b * BATCH + r;
            float S = ((sS[r][0] + sS[r][1]) + (sS[r][2] + sS[r][3]))
                    + ((sS[r][4] + sS[r][5]) + (sS[r][6] + sS[r][7]));
            float lse = (M[r] + log2f(S)) * LN2;
            float res = -eps * (LOGW + lse);
            if (args.avg[var]) res = 0.5f * (args.oldpot[var][row] + res);
            args.out[var][row] = res;
        }
        __syncthreads();   // sA/sS safe for reuse; buf safe for refill

        // refill the just-freed buffer with batch b+2
        if (b + 2 < NBATCH) SM_ISSUE_BATCH(b + 2, buf);
    }
}
#undef SM_ISSUE_BATCH

// ---------------- final reduction ----------------
__global__ void final_reduce(float* __restrict__ out) {
    __shared__ float sh[1024];
    int t = threadIdx.x;
    float s = 0.0f;
    for (int i = t; i < NPTS; i += 1024)
        s += (d_ffin[i] - d_xfin[i]) + (d_gfin[i] - d_yfin[i]);
    sh[t] = s;
    __syncthreads();
    for (int off = 512; off > 0; off >>= 1) {
        if (t < off) sh[t] += sh[t + off];
        __syncthreads();
    }
    if (t == 0) out[0] = sh[0] / (float)NPTS;
}

// ---------------- host ----------------
static void* symaddr(const void* sym) {
    void* p = nullptr;
    cudaGetSymbolAddress(&p, sym);
    return p;
}

#define GEMM_SMEM 65536

extern "C" void kernel_launch(void* const* d_in, const int* in_sizes, int n_in,
                              void* d_out, int out_size) {
    const float* x1 = (const float*)d_in[0];
    const float* x2 = (const float*)d_in[1];
    const float* w  = (const float*)d_in[2];

    __half* an  = (__half*)symaddr(d_anh);
    __half* bn  = (__half*)symaddr(d_bnh);
    __half* Gxy = (__half*)symaddr(d_Gxy);
    __half* Gyx = (__half*)symaddr(d_Gyx);
    __half* Gxx = (__half*)symaddr(d_Gxx);
    __half* Gyy = (__half*)symaddr(d_Gyy);
    float* fb  = (float*)symaddr(d_f);
    float* gb  = (float*)symaddr(d_g);
    float* xb  = (float*)symaddr(d_fxx);
    float* yb  = (float*)symaddr(d_gyy);
    float* ffin = (float*)symaddr(d_ffin);
    float* gfin = (float*)symaddr(d_gfin);
    float* xfin = (float*)symaddr(d_xfin);
    float* yfin = (float*)symaddr(d_yfin);

    cudaFuncSetAttribute(gemm_mma, cudaFuncAttributeMaxDynamicSharedMemorySize, GEMM_SMEM);
    cudaFuncSetAttribute(softmin4, cudaFuncAttributeMaxDynamicSharedMemorySize, SM_SOFTMIN);

    wprep_kernel<<<1, DIM>>>(w);
    rownorm_kernel<<<2 * NPTS, DIM>>>(x1, x2);
    zero_kernel<<<NPTS / 256, 256>>>();

    dim3 ggrid(NPTS / 128, NPTS / 128);
    gemm_mma<<<ggrid, 256, GEMM_SMEM>>>(an, bn, Gxy, Gyx, 0);
    gemm_mma<<<ggrid, 256, GEMM_SMEM>>>(an, an, Gxx, Gxx, 1);
    gemm_mma<<<ggrid, 256, GEMM_SMEM>>>(bn, bn, Gyy, Gyy, 1);

    const float eps_list[10] = {4.0f, 1.0f, 0.25f, 0.0625f, 0.015625f,
                                0.00390625f, 0.0025f, 0.0025f, 0.0025f, 0.0025f};
    dim3 sgrid(NPTS / RPBLK, 4);
    int cur = 0;
    for (int i = 0; i < 10; ++i) {
        float eps = eps_list[i];
        int nxt = 1 - cur;
        SMArgs a;
        a.G[0] = Gxx;  a.pot[0] = xb + cur * NPTS; a.oldpot[0] = xb + cur * NPTS; a.out[0] = xb + nxt * NPTS; a.avg[0] = 1;
        a.G[1] = Gyy;  a.pot[1] = yb + cur * NPTS; a.oldpot[1] = yb + cur * NPTS; a.out[1] = yb + nxt * NPTS; a.avg[1] = 1;
        a.G[2] = Gxy;  a.pot[2] = gb + cur * NPTS; a.oldpot[2] = nullptr;         a.out[2] = fb + nxt * NPTS; a.avg[2] = 0;
        a.G[3] = Gyx;  a.pot[3] = fb + cur * NPTS; a.oldpot[3] = nullptr;         a.out[3] = gb + nxt * NPTS; a.avg[3] = 0;
        softmin4<<<sgrid, 256, SM_SOFTMIN>>>(a, eps);
        cur = nxt;
    }

    const float epsF = 0.0025f;
    {
        SMArgs a;
        a.G[0] = Gxy; a.pot[0] = gb + cur * NPTS; a.oldpot[0] = nullptr; a.out[0] = ffin; a.avg[0] = 0;
        a.G[1] = Gyx; a.pot[1] = fb + cur * NPTS; a.oldpot[1] = nullptr; a.out[1] = gfin; a.avg[1] = 0;
        a.G[2] = Gxx; a.pot[2] = xb + cur * NPTS; a.oldpot[2] = nullptr; a.out[2] = xfin; a.avg[2] = 0;
        a.G[3] = Gyy; a.pot[3] = yb + cur * NPTS; a.oldpot[3] = nullptr; a.out[3] = yfin; a.avg[3] = 0;
        softmin4<<<sgrid, 256, SM_SOFTMIN>>>(a, epsF);
    }

    final_reduce<<<1, 1024>>>((float*)d_out);
}

// round 12
// speedup vs baseline: 1.2374x; 1.0619x over previous
#include <cuda_runtime.h>
#include <cuda_fp16.h>
#include <math.h>
#include <stdint.h>

#define NPTS 8192
#define DIM 256
#define KC 64
#define NCHUNK (DIM / KC)
#define RPB 4
#define SM_SOFTMIN (RPB * 16384)   // 64 KB staged G

// ---------------- static device scratch (no allocation allowed) ----------------
__device__ float  d_wc[DIM];
__device__ __half d_anh[(size_t)NPTS * DIM];
__device__ __half d_bnh[(size_t)NPTS * DIM];
__device__ __half d_Gxy[(size_t)NPTS * NPTS];
__device__ __half d_Gyx[(size_t)NPTS * NPTS];
__device__ __half d_Gxx[(size_t)NPTS * NPTS];
__device__ __half d_Gyy[(size_t)NPTS * NPTS];
__device__ float  d_f[2][NPTS];
__device__ float  d_g[2][NPTS];
__device__ float  d_fxx[2][NPTS];
__device__ float  d_gyy[2][NPTS];
__device__ float  d_ffin[NPTS], d_gfin[NPTS], d_xfin[NPTS], d_yfin[NPTS];

__device__ __forceinline__ float ex2f_fast(float x) {
    float y; asm("ex2.approx.ftz.f32 %0, %1;" : "=f"(y) : "f"(x)); return y;
}
__device__ __forceinline__ uint32_t smem_u32(const void* p) {
    uint32_t a;
    asm("{ .reg .u64 t; cvta.to.shared.u64 t, %1; cvt.u32.u64 %0, t; }" : "=r"(a) : "l"(p));
    return a;
}
__device__ __forceinline__ void cp_async16(uint32_t dst, const void* src) {
    asm volatile("cp.async.cg.shared.global [%0], [%1], 16;" :: "r"(dst), "l"(src) : "memory");
}
#define LDMX4(r, addr)                                                          \
    asm volatile("ldmatrix.sync.aligned.m8n8.x4.shared.b16 {%0,%1,%2,%3}, [%4];" \
                 : "=r"((r)[0]), "=r"((r)[1]), "=r"((r)[2]), "=r"((r)[3])        \
                 : "r"(addr))

// ---------------- prep ----------------
__global__ void wprep_kernel(const float* __restrict__ w) {
    __shared__ float sh[DIM];
    int t = threadIdx.x;
    float c = fminf(fmaxf(w[t], 0.0f), 2.0f);
    sh[t] = c;
    __syncthreads();
    for (int off = DIM / 2; off > 0; off >>= 1) {
        if (t < off) sh[t] += sh[t + off];
        __syncthreads();
    }
    d_wc[t] = c * ((float)DIM / sh[0]);
}

__global__ void rownorm_kernel(const float* __restrict__ x1, const float* __restrict__ x2) {
    __shared__ float sh[DIM];
    int b = blockIdx.x, t = threadIdx.x;
    float v;
    if (b < NPTS) v = d_wc[t] * x1[(size_t)b * DIM + t];
    else          v = x2[(size_t)(b - NPTS) * DIM + t];
    sh[t] = v * v;
    __syncthreads();
    for (int off = DIM / 2; off > 0; off >>= 1) {
        if (t < off) sh[t] += sh[t + off];
        __syncthreads();
    }
    float inv = 1.0f / (sqrtf(sh[0]) + 1e-12f);
    __half h = __float2half_rn(v * inv);
    if (b < NPTS) d_anh[(size_t)b * DIM + t] = h;
    else          d_bnh[(size_t)(b - NPTS) * DIM + t] = h;
}

__global__ void zero_kernel() {
    int i = blockIdx.x * blockDim.x + threadIdx.x;
    if (i < NPTS) {
        d_f[0][i] = 0.0f; d_g[0][i] = 0.0f;
        d_fxx[0][i] = 0.0f; d_gyy[0][i] = 0.0f;
    }
}

// ---------------- HMMA GEMM: 3 problems in one launch (blockIdx.z) ----------------
struct GArgs {
    const __half* A[3];
    const __half* B[3];
    __half*       C[3];
    __half*       CT[3];
    int           sym[3];
};

__global__ void __launch_bounds__(256, 2) gemm_mma(GArgs ga) {
    extern __shared__ char smem[];
    const int prob = blockIdx.z;
    const int btx = blockIdx.x, bty = blockIdx.y;
    const int sym = ga.sym[prob];
    if (sym && btx > bty) return;
    const __half* A  = ga.A[prob];
    const __half* B  = ga.B[prob];
    __half*       C  = ga.C[prob];
    __half*       CT = ga.CT[prob];

    const uint32_t smem_base = smem_u32(smem);
    const int tid = threadIdx.x;
    const int wid = tid >> 5, lane = tid & 31;
    const int warp_m = wid >> 2, warp_n = wid & 3;
    const int rowBase = bty * 128;
    const int colBase = btx * 128;

    const int mat = lane >> 3, rin = lane & 7;
    const int a_row_in = (mat & 1) * 8 + rin;
    const int a_kh     = (mat >> 1) * 8;
    const int b_row_in = (mat >> 1) * 8 + rin;
    const int b_kh     = (mat & 1) * 8;

    float acc[4][4][4];
#pragma unroll
    for (int mi = 0; mi < 4; ++mi)
#pragma unroll
        for (int ni = 0; ni < 4; ++ni)
#pragma unroll
            for (int q = 0; q < 4; ++q) acc[mi][ni][q] = 0.0f;

#define ISSUE_CHUNK(c, b) do {                                                  \
        const __half* Asrc_ = A + (size_t)rowBase * DIM + (c) * KC;             \
        const __half* Bsrc_ = B + (size_t)colBase * DIM + (c) * KC;             \
        uint32_t Ab_ = smem_base + (b) * 32768;                                 \
        uint32_t Bb_ = Ab_ + 16384;                                             \
        _Pragma("unroll")                                                       \
        for (int q_ = 0; q_ < 4; ++q_) {                                        \
            int i_ = q_ * 256 + tid;                                            \
            int r_ = i_ >> 3, cw_ = i_ & 7;                                     \
            uint32_t off_ = r_ * 128 + (((uint32_t)(cw_ ^ (r_ & 7))) << 4);     \
            cp_async16(Ab_ + off_, Asrc_ + (size_t)r_ * DIM + cw_ * 8);         \
            cp_async16(Bb_ + off_, Bsrc_ + (size_t)r_ * DIM + cw_ * 8);         \
        }                                                                       \
        asm volatile("cp.async.commit_group;" ::: "memory");                    \
    } while (0)

    ISSUE_CHUNK(0, 0);
#pragma unroll
    for (int c = 0; c < NCHUNK; ++c) {
        if (c + 1 < NCHUNK) {
            ISSUE_CHUNK(c + 1, (c + 1) & 1);
            asm volatile("cp.async.wait_group 1;" ::: "memory");
        } else {
            asm volatile("cp.async.wait_group 0;" ::: "memory");
        }
        __syncthreads();
        uint32_t Ab = smem_base + (c & 1) * 32768;
        uint32_t Bb = Ab + 16384;
#pragma unroll
        for (int ks = 0; ks < 4; ++ks) {
            uint32_t bf[2][4];
#pragma unroll
            for (int p = 0; p < 2; ++p) {
                int nrow = warp_n * 32 + p * 16 + b_row_in;
                int kcol = ks * 16 + b_kh;
                uint32_t addr = Bb + nrow * 128 + ((uint32_t)((kcol >> 3) ^ (nrow & 7)) << 4);
                LDMX4(bf[p], addr);
            }
#pragma unroll
            for (int mi = 0; mi < 4; ++mi) {
                uint32_t af[4];
                int arow = warp_m * 64 + mi * 16 + a_row_in;
                int kcol = ks * 16 + a_kh;
                uint32_t addr = Ab + arow * 128 + ((uint32_t)((kcol >> 3) ^ (arow & 7)) << 4);
                LDMX4(af, addr);
#pragma unroll
                for (int ni = 0; ni < 4; ++ni) {
                    asm volatile(
                        "mma.sync.aligned.m16n8k16.row.col.f32.f16.f16.f32 "
                        "{%0,%1,%2,%3}, {%4,%5,%6,%7}, {%8,%9}, {%0,%1,%2,%3};"
                        : "+f"(acc[mi][ni][0]), "+f"(acc[mi][ni][1]),
                          "+f"(acc[mi][ni][2]), "+f"(acc[mi][ni][3])
                        : "r"(af[0]), "r"(af[1]), "r"(af[2]), "r"(af[3]),
                          "r"(bf[ni >> 1][(ni & 1) * 2]), "r"(bf[ni >> 1][(ni & 1) * 2 + 1]));
                }
            }
        }
        __syncthreads();
    }
#undef ISSUE_CHUNK

    __half* stage = (__half*)smem;
#pragma unroll
    for (int mi = 0; mi < 4; ++mi)
#pragma unroll
        for (int ni = 0; ni < 4; ++ni) {
            int row = warp_m * 64 + mi * 16 + (lane >> 2);
            int col = warp_n * 32 + ni * 8 + 2 * (lane & 3);
            __half2 lo = __floats2half2_rn(acc[mi][ni][0], acc[mi][ni][1]);
            __half2 hi = __floats2half2_rn(acc[mi][ni][2], acc[mi][ni][3]);
            *(__half2*)(stage + row * 136 + col)       = lo;
            *(__half2*)(stage + (row + 8) * 136 + col) = hi;
        }
    __syncthreads();
#pragma unroll
    for (int i = tid; i < 2048; i += 256) {
        int r = i >> 4, ch = i & 15;
        uint4 v = *(uint4*)(stage + r * 136 + ch * 8);
        *(uint4*)(C + (size_t)(rowBase + r) * NPTS + colBase + ch * 8) = v;
    }

    if (!(sym && btx == bty)) {
        __syncthreads();
#pragma unroll
        for (int mi = 0; mi < 4; ++mi)
#pragma unroll
            for (int ni = 0; ni < 4; ++ni) {
                int row = warp_m * 64 + mi * 16 + (lane >> 2);
                int col = warp_n * 32 + ni * 8 + 2 * (lane & 3);
                stage[col * 136 + row]           = __float2half_rn(acc[mi][ni][0]);
                stage[(col + 1) * 136 + row]     = __float2half_rn(acc[mi][ni][1]);
                stage[col * 136 + row + 8]       = __float2half_rn(acc[mi][ni][2]);
                stage[(col + 1) * 136 + row + 8] = __float2half_rn(acc[mi][ni][3]);
            }
        __syncthreads();
#pragma unroll
        for (int i = tid; i < 2048; i += 256) {
            int r = i >> 4, ch = i & 15;
            uint4 v = *(uint4*)(stage + r * 136 + ch * 8);
            *(uint4*)(CT + (size_t)(colBase + r) * NPTS + rowBase + ch * 8) = v;
        }
    }
}

// ---------------- dense softmin (R7 structure, half2 pass A) ----------------
struct SMArgs {
    const __half* G[4];
    const float*  pot[4];
    const float*  oldpot[4];
    float*        out[4];
    int           avg[4];
};

__global__ void __launch_bounds__(256, 3) softmin4(SMArgs args, float eps) {
    extern __shared__ char smg[];               // RPB * 16 KB
    const uint32_t smg_u = smem_u32(smg);
    const int var  = blockIdx.y;
    const int row0 = blockIdx.x * RPB;
    const int tid  = threadIdx.x;
    const int lane = tid & 31, wid = tid >> 5;

    const float L2E = 1.4426950408889634f;
    const float c1 = L2E / eps;
    const float c0 = -c1;

    // ---- issue all G copies (64 KB, 16 x 16B per thread) ----
    const __half* Gbase = args.G[var];
#pragma unroll
    for (int r = 0; r < RPB; ++r) {
        const __half* Gr = Gbase + (size_t)(row0 + r) * NPTS;
#pragma unroll
        for (int q = 0; q < 4; ++q) {
            int idx = q * 256 + tid;
            cp_async16(smg_u + r * 16384 + idx * 16, Gr + idx * 8);
        }
    }
    asm volatile("cp.async.commit_group;" ::: "memory");

    // ---- fold pot while copies fly ----
    const float* pot = args.pot[var];
    float pp[32];
#pragma unroll
    for (int it = 0; it < 4; ++it) {
        int idx = it * 256 + tid;
        float4 a = ((const float4*)pot)[2 * idx];
        float4 b = ((const float4*)pot)[2 * idx + 1];
        pp[8 * it + 0] = fmaf(a.x, c1, c0); pp[8 * it + 1] = fmaf(a.y, c1, c0);
        pp[8 * it + 2] = fmaf(a.z, c1, c0); pp[8 * it + 3] = fmaf(a.w, c1, c0);
        pp[8 * it + 4] = fmaf(b.x, c1, c0); pp[8 * it + 5] = fmaf(b.y, c1, c0);
        pp[8 * it + 6] = fmaf(b.z, c1, c0); pp[8 * it + 7] = fmaf(b.w, c1, c0);
    }
    // half2 copies of pp for pass A (pairs match half2 lanes of G chunks)
    __half2 pph2[16];
#pragma unroll
    for (int j = 0; j < 16; ++j)
        pph2[j] = __floats2half2_rn(pp[2 * j], pp[2 * j + 1]);
    const __half2 c1h2 = __floats2half2_rn(c1, c1);

    asm volatile("cp.async.wait_group 0;" ::: "memory");

    __shared__ float sA[RPB][8];
    __shared__ float sS[RPB][8];

    // ---- pass A: per-row approximate max in half2 (exact-safe: any M works) ----
    float wtm[RPB];
#pragma unroll
    for (int r = 0; r < RPB; ++r) {
        __half2 mh = __floats2half2_rn(-60000.0f, -60000.0f);
#pragma unroll
        for (int it = 0; it < 4; ++it) {
            uint4 q = *(const uint4*)(smg + r * 16384 + (it * 256 + tid) * 16);
            const __half2* g2 = (const __half2*)&q;
#pragma unroll
            for (int k = 0; k < 4; ++k)
                mh = __hmax2(mh, __hfma2(g2[k], c1h2, pph2[it * 4 + k]));
        }
        float2 mf = __half22float2(mh);
        float tm = fmaxf(mf.x, mf.y);
#pragma unroll
        for (int off = 16; off > 0; off >>= 1)
            tm = fmaxf(tm, __shfl_xor_sync(0xffffffffu, tm, off));
        wtm[r] = tm;
        if (lane == 0) sA[r][wid] = tm;
    }
    __syncthreads();
    float M[RPB];
#pragma unroll
    for (int r = 0; r < RPB; ++r) {
        float m = sA[r][0];
#pragma unroll
        for (int i = 1; i < 8; ++i) m = fmaxf(m, sA[r][i]);
        M[r] = m;
    }

    // ---- pass B: fp32 exp-sum, contributing warps only (threshold margin
    //      36 < 40 absorbs half-precision slack in wtm/M) ----
#pragma unroll
    for (int r = 0; r < RPB; ++r) {
        float s = 0.0f;
        if (wtm[r] >= M[r] - 36.0f) {
            float Mr = M[r];
            float s0 = 0.f, s1 = 0.f, s2 = 0.f, s3 = 0.f;
#pragma unroll
            for (int it = 0; it < 4; ++it) {
                uint4 q = *(const uint4*)(smg + r * 16384 + (it * 256 + tid) * 16);
                float2 g0 = __half22float2(*(const __half2*)&q.x);
                float2 g1 = __half22float2(*(const __half2*)&q.y);
                float2 g2 = __half22float2(*(const __half2*)&q.z);
                float2 g3 = __half22float2(*(const __half2*)&q.w);
                s0 += ex2f_fast(fmaf(g0.x, c1, pp[8 * it + 0]) - Mr);
                s1 += ex2f_fast(fmaf(g0.y, c1, pp[8 * it + 1]) - Mr);
                s2 += ex2f_fast(fmaf(g1.x, c1, pp[8 * it + 2]) - Mr);
                s3 += ex2f_fast(fmaf(g1.y, c1, pp[8 * it + 3]) - Mr);
                s0 += ex2f_fast(fmaf(g2.x, c1, pp[8 * it + 4]) - Mr);
                s1 += ex2f_fast(fmaf(g2.y, c1, pp[8 * it + 5]) - Mr);
                s2 += ex2f_fast(fmaf(g3.x, c1, pp[8 * it + 6]) - Mr);
                s3 += ex2f_fast(fmaf(g3.y, c1, pp[8 * it + 7]) - Mr);
            }
            s = (s0 + s1) + (s2 + s3);
        }
#pragma unroll
        for (int off = 16; off > 0; off >>= 1)
            s += __shfl_xor_sync(0xffffffffu, s, off);
        if (lane == 0) sS[r][wid] = s;
    }
    __syncthreads();

    if (tid < RPB) {
        int r = tid;
        float S = ((sS[r][0] + sS[r][1]) + (sS[r][2] + sS[r][3]))
                + ((sS[r][4] + sS[r][5]) + (sS[r][6] + sS[r][7]));
        const float LOGW = -9.010913347279288f;   // -log(8192)
        const float LN2  = 0.6931471805599453f;
        float lse = (M[r] + log2f(S)) * LN2;
        float res = -eps * (LOGW + lse);
        if (args.avg[var]) res = 0.5f * (args.oldpot[var][row0 + r] + res);
        args.out[var][row0 + r] = res;
    }
}

// ---------------- final reduction ----------------
__global__ void final_reduce(float* __restrict__ out) {
    __shared__ float sh[1024];
    int t = threadIdx.x;
    float s = 0.0f;
    for (int i = t; i < NPTS; i += 1024)
        s += (d_ffin[i] - d_xfin[i]) + (d_gfin[i] - d_yfin[i]);
    sh[t] = s;
    __syncthreads();
    for (int off = 512; off > 0; off >>= 1) {
        if (t < off) sh[t] += sh[t + off];
        __syncthreads();
    }
    if (t == 0) out[0] = sh[0] / (float)NPTS;
}

// ---------------- host ----------------
static void* symaddr(const void* sym) {
    void* p = nullptr;
    cudaGetSymbolAddress(&p, sym);
    return p;
}

#define GEMM_SMEM 65536

extern "C" void kernel_launch(void* const* d_in, const int* in_sizes, int n_in,
                              void* d_out, int out_size) {
    const float* x1 = (const float*)d_in[0];
    const float* x2 = (const float*)d_in[1];
    const float* w  = (const float*)d_in[2];

    __half* an  = (__half*)symaddr(d_anh);
    __half* bn  = (__half*)symaddr(d_bnh);
    __half* Gxy = (__half*)symaddr(d_Gxy);
    __half* Gyx = (__half*)symaddr(d_Gyx);
    __half* Gxx = (__half*)symaddr(d_Gxx);
    __half* Gyy = (__half*)symaddr(d_Gyy);
    float* fb  = (float*)symaddr(d_f);
    float* gb  = (float*)symaddr(d_g);
    float* xb  = (float*)symaddr(d_fxx);
    float* yb  = (float*)symaddr(d_gyy);
    float* ffin = (float*)symaddr(d_ffin);
    float* gfin = (float*)symaddr(d_gfin);
    float* xfin = (float*)symaddr(d_xfin);
    float* yfin = (float*)symaddr(d_yfin);

    cudaFuncSetAttribute(gemm_mma, cudaFuncAttributeMaxDynamicSharedMemorySize, GEMM_SMEM);
    cudaFuncSetAttribute(softmin4, cudaFuncAttributeMaxDynamicSharedMemorySize, SM_SOFTMIN);

    wprep_kernel<<<1, DIM>>>(w);
    rownorm_kernel<<<2 * NPTS, DIM>>>(x1, x2);
    zero_kernel<<<NPTS / 256, 256>>>();

    {
        GArgs ga;
        ga.A[0] = an; ga.B[0] = bn; ga.C[0] = Gxy; ga.CT[0] = Gyx; ga.sym[0] = 0;
        ga.A[1] = an; ga.B[1] = an; ga.C[1] = Gxx; ga.CT[1] = Gxx; ga.sym[1] = 1;
        ga.A[2] = bn; ga.B[2] = bn; ga.C[2] = Gyy; ga.CT[2] = Gyy; ga.sym[2] = 1;
        gemm_mma<<<dim3(NPTS / 128, NPTS / 128, 3), 256, GEMM_SMEM>>>(ga);
    }

    const float eps_list[10] = {4.0f, 1.0f, 0.25f, 0.0625f, 0.015625f,
                                0.00390625f, 0.0025f, 0.0025f, 0.0025f, 0.0025f};
    dim3 sgrid(NPTS / RPB, 4);
    int cur = 0;
    for (int i = 0; i < 10; ++i) {
        float eps = eps_list[i];
        int nxt = 1 - cur;
        SMArgs a;
        a.G[0] = Gxx;  a.pot[0] = xb + cur * NPTS; a.oldpot[0] = xb + cur * NPTS; a.out[0] = xb + nxt * NPTS; a.avg[0] = 1;
        a.G[1] = Gyy;  a.pot[1] = yb + cur * NPTS; a.oldpot[1] = yb + cur * NPTS; a.out[1] = yb + nxt * NPTS; a.avg[1] = 1;
        a.G[2] = Gxy;  a.pot[2] = gb + cur * NPTS; a.oldpot[2] = nullptr;         a.out[2] = fb + nxt * NPTS; a.avg[2] = 0;
        a.G[3] = Gyx;  a.pot[3] = fb + cur * NPTS; a.oldpot[3] = nullptr;         a.out[3] = gb + nxt * NPTS; a.avg[3] = 0;
        softmin4<<<sgrid, 256, SM_SOFTMIN>>>(a, eps);
        cur = nxt;
    }

    const float epsF = 0.0025f;
    {
        SMArgs a;
        a.G[0] = Gxy; a.pot[0] = gb + cur * NPTS; a.oldpot[0] = nullptr; a.out[0] = ffin; a.avg[0] = 0;
        a.G[1] = Gyx; a.pot[1] = fb + cur * NPTS; a.oldpot[1] = nullptr; a.out[1] = gfin; a.avg[1] = 0;
        a.G[2] = Gxx; a.pot[2] = xb + cur * NPTS; a.oldpot[2] = nullptr; a.out[2] = xfin; a.avg[2] = 0;
        a.G[3] = Gyy; a.pot[3] = yb + cur * NPTS; a.oldpot[3] = nullptr; a.out[3] = yfin; a.avg[3] = 0;
        softmin4<<<sgrid, 256, SM_SOFTMIN>>>(a, epsF);
    }

    final_reduce<<<1, 1024>>>((float*)d_out);
}

// round 13
// speedup vs baseline: 1.2388x; 1.0011x over previous
#include <cuda_runtime.h>
#include <cuda_fp16.h>
#include <math.h>
#include <stdint.h>

#define NPTS 8192
#define DIM 256
#define KC 64
#define NCHUNK (DIM / KC)
#define RPB 4
#define SM_SOFTMIN (RPB * 16384)   // 64 KB staged G
#define GEMM_SMEM 98304            // 3 x 32 KB pipeline buffers

// ---------------- static device scratch (no allocation allowed) ----------------
__device__ float  d_wc[DIM];
__device__ __half d_anh[(size_t)NPTS * DIM];
__device__ __half d_bnh[(size_t)NPTS * DIM];
__device__ __half d_Gxy[(size_t)NPTS * NPTS];
__device__ __half d_Gyx[(size_t)NPTS * NPTS];
__device__ __half d_Gxx[(size_t)NPTS * NPTS];
__device__ __half d_Gyy[(size_t)NPTS * NPTS];
__device__ float  d_f[2][NPTS];
__device__ float  d_g[2][NPTS];
__device__ float  d_fxx[2][NPTS];
__device__ float  d_gyy[2][NPTS];
__device__ float  d_ffin[NPTS], d_gfin[NPTS], d_xfin[NPTS], d_yfin[NPTS];

__device__ __forceinline__ float ex2f_fast(float x) {
    float y; asm("ex2.approx.ftz.f32 %0, %1;" : "=f"(y) : "f"(x)); return y;
}
__device__ __forceinline__ uint32_t smem_u32(const void* p) {
    uint32_t a;
    asm("{ .reg .u64 t; cvta.to.shared.u64 t, %1; cvt.u32.u64 %0, t; }" : "=r"(a) : "l"(p));
    return a;
}
__device__ __forceinline__ void cp_async16(uint32_t dst, const void* src) {
    asm volatile("cp.async.cg.shared.global [%0], [%1], 16;" :: "r"(dst), "l"(src) : "memory");
}
#define LDMX4(r, addr)                                                          \
    asm volatile("ldmatrix.sync.aligned.m8n8.x4.shared.b16 {%0,%1,%2,%3}, [%4];" \
                 : "=r"((r)[0]), "=r"((r)[1]), "=r"((r)[2]), "=r"((r)[3])        \
                 : "r"(addr))

// ---------------- prep ----------------
__global__ void wprep_kernel(const float* __restrict__ w) {
    __shared__ float sh[DIM];
    int t = threadIdx.x;
    float c = fminf(fmaxf(w[t], 0.0f), 2.0f);
    sh[t] = c;
    __syncthreads();
    for (int off = DIM / 2; off > 0; off >>= 1) {
        if (t < off) sh[t] += sh[t + off];
        __syncthreads();
    }
    d_wc[t] = c * ((float)DIM / sh[0]);
}

__global__ void rownorm_kernel(const float* __restrict__ x1, const float* __restrict__ x2) {
    __shared__ float sh[DIM];
    int b = blockIdx.x, t = threadIdx.x;
    float v;
    if (b < NPTS) v = d_wc[t] * x1[(size_t)b * DIM + t];
    else          v = x2[(size_t)(b - NPTS) * DIM + t];
    sh[t] = v * v;
    __syncthreads();
    for (int off = DIM / 2; off > 0; off >>= 1) {
        if (t < off) sh[t] += sh[t + off];
        __syncthreads();
    }
    float inv = 1.0f / (sqrtf(sh[0]) + 1e-12f);
    __half h = __float2half_rn(v * inv);
    if (b < NPTS) d_anh[(size_t)b * DIM + t] = h;
    else          d_bnh[(size_t)(b - NPTS) * DIM + t] = h;
}

__global__ void zero_kernel() {
    int i = blockIdx.x * blockDim.x + threadIdx.x;
    if (i < NPTS) {
        d_f[0][i] = 0.0f; d_g[0][i] = 0.0f;
        d_fxx[0][i] = 0.0f; d_gyy[0][i] = 0.0f;
    }
}

// ---------------- HMMA GEMM: 3 problems in one launch, 3-stage cp.async ----------------
struct GArgs {
    const __half* A[3];
    const __half* B[3];
    __half*       C[3];
    __half*       CT[3];
    int           sym[3];
};

__global__ void __launch_bounds__(256, 2) gemm_mma(GArgs ga) {
    extern __shared__ char smem[];
    const int prob = blockIdx.z;
    const int btx = blockIdx.x, bty = blockIdx.y;
    const int sym = ga.sym[prob];
    if (sym && btx > bty) return;
    const __half* A  = ga.A[prob];
    const __half* B  = ga.B[prob];
    __half*       C  = ga.C[prob];
    __half*       CT = ga.CT[prob];

    const uint32_t smem_base = smem_u32(smem);
    const int tid = threadIdx.x;
    const int wid = tid >> 5, lane = tid & 31;
    const int warp_m = wid >> 2, warp_n = wid & 3;
    const int rowBase = bty * 128;
    const int colBase = btx * 128;

    const int mat = lane >> 3, rin = lane & 7;
    const int a_row_in = (mat & 1) * 8 + rin;
    const int a_kh     = (mat >> 1) * 8;
    const int b_row_in = (mat >> 1) * 8 + rin;
    const int b_kh     = (mat & 1) * 8;

    float acc[4][4][4];
#pragma unroll
    for (int mi = 0; mi < 4; ++mi)
#pragma unroll
        for (int ni = 0; ni < 4; ++ni)
#pragma unroll
            for (int q = 0; q < 4; ++q) acc[mi][ni][q] = 0.0f;

#define ISSUE_CHUNK(c, b) do {                                                  \
        const __half* Asrc_ = A + (size_t)rowBase * DIM + (c) * KC;             \
        const __half* Bsrc_ = B + (size_t)colBase * DIM + (c) * KC;             \
        uint32_t Ab_ = smem_base + (b) * 32768;                                 \
        uint32_t Bb_ = Ab_ + 16384;                                             \
        _Pragma("unroll")                                                       \
        for (int q_ = 0; q_ < 4; ++q_) {                                        \
            int i_ = q_ * 256 + tid;                                            \
            int r_ = i_ >> 3, cw_ = i_ & 7;                                     \
            uint32_t off_ = r_ * 128 + (((uint32_t)(cw_ ^ (r_ & 7))) << 4);     \
            cp_async16(Ab_ + off_, Asrc_ + (size_t)r_ * DIM + cw_ * 8);         \
            cp_async16(Bb_ + off_, Bsrc_ + (size_t)r_ * DIM + cw_ * 8);         \
        }                                                                       \
        asm volatile("cp.async.commit_group;" ::: "memory");                    \
    } while (0)

    // 3-stage pipeline: two chunks always in flight
    ISSUE_CHUNK(0, 0);
    ISSUE_CHUNK(1, 1);
#pragma unroll
    for (int c = 0; c < NCHUNK; ++c) {
        if (c + 2 < NCHUNK) ISSUE_CHUNK(c + 2, (c + 2) % 3);
        if (c <= NCHUNK - 3)      asm volatile("cp.async.wait_group 2;" ::: "memory");
        else if (c == NCHUNK - 2) asm volatile("cp.async.wait_group 1;" ::: "memory");
        else                      asm volatile("cp.async.wait_group 0;" ::: "memory");
        __syncthreads();
        uint32_t Ab = smem_base + (c % 3) * 32768;
        uint32_t Bb = Ab + 16384;
#pragma unroll
        for (int ks = 0; ks < 4; ++ks) {
            uint32_t bf[2][4];
#pragma unroll
            for (int p = 0; p < 2; ++p) {
                int nrow = warp_n * 32 + p * 16 + b_row_in;
                int kcol = ks * 16 + b_kh;
                uint32_t addr = Bb + nrow * 128 + ((uint32_t)((kcol >> 3) ^ (nrow & 7)) << 4);
                LDMX4(bf[p], addr);
            }
#pragma unroll
            for (int mi = 0; mi < 4; ++mi) {
                uint32_t af[4];
                int arow = warp_m * 64 + mi * 16 + a_row_in;
                int kcol = ks * 16 + a_kh;
                uint32_t addr = Ab + arow * 128 + ((uint32_t)((kcol >> 3) ^ (arow & 7)) << 4);
                LDMX4(af, addr);
#pragma unroll
                for (int ni = 0; ni < 4; ++ni) {
                    asm volatile(
                        "mma.sync.aligned.m16n8k16.row.col.f32.f16.f16.f32 "
                        "{%0,%1,%2,%3}, {%4,%5,%6,%7}, {%8,%9}, {%0,%1,%2,%3};"
                        : "+f"(acc[mi][ni][0]), "+f"(acc[mi][ni][1]),
                          "+f"(acc[mi][ni][2]), "+f"(acc[mi][ni][3])
                        : "r"(af[0]), "r"(af[1]), "r"(af[2]), "r"(af[3]),
                          "r"(bf[ni >> 1][(ni & 1) * 2]), "r"(bf[ni >> 1][(ni & 1) * 2 + 1]));
                }
            }
        }
        __syncthreads();
    }
#undef ISSUE_CHUNK

    __half* stage = (__half*)smem;
#pragma unroll
    for (int mi = 0; mi < 4; ++mi)
#pragma unroll
        for (int ni = 0; ni < 4; ++ni) {
            int row = warp_m * 64 + mi * 16 + (lane >> 2);
            int col = warp_n * 32 + ni * 8 + 2 * (lane & 3);
            __half2 lo = __floats2half2_rn(acc[mi][ni][0], acc[mi][ni][1]);
            __half2 hi = __floats2half2_rn(acc[mi][ni][2], acc[mi][ni][3]);
            *(__half2*)(stage + row * 136 + col)       = lo;
            *(__half2*)(stage + (row + 8) * 136 + col) = hi;
        }
    __syncthreads();
#pragma unroll
    for (int i = tid; i < 2048; i += 256) {
        int r = i >> 4, ch = i & 15;
        uint4 v = *(uint4*)(stage + r * 136 + ch * 8);
        *(uint4*)(C + (size_t)(rowBase + r) * NPTS + colBase + ch * 8) = v;
    }

    if (!(sym && btx == bty)) {
        __syncthreads();
#pragma unroll
        for (int mi = 0; mi < 4; ++mi)
#pragma unroll
            for (int ni = 0; ni < 4; ++ni) {
                int row = warp_m * 64 + mi * 16 + (lane >> 2);
                int col = warp_n * 32 + ni * 8 + 2 * (lane & 3);
                stage[col * 136 + row]           = __float2half_rn(acc[mi][ni][0]);
                stage[(col + 1) * 136 + row]     = __float2half_rn(acc[mi][ni][1]);
                stage[col * 136 + row + 8]       = __float2half_rn(acc[mi][ni][2]);
                stage[(col + 1) * 136 + row + 8] = __float2half_rn(acc[mi][ni][3]);
            }
        __syncthreads();
#pragma unroll
        for (int i = tid; i < 2048; i += 256) {
            int r = i >> 4, ch = i & 15;
            uint4 v = *(uint4*)(stage + r * 136 + ch * 8);
            *(uint4*)(CT + (size_t)(colBase + r) * NPTS + rowBase + ch * 8) = v;
        }
    }
}

// ---------------- dense softmin (R7 structure, half2 pass A) ----------------
struct SMArgs {
    const __half* G[4];
    const float*  pot[4];
    const float*  oldpot[4];
    float*        out[4];
    int           avg[4];
};

__global__ void __launch_bounds__(256, 3) softmin4(SMArgs args, float eps) {
    extern __shared__ char smg[];               // RPB * 16 KB
    const uint32_t smg_u = smem_u32(smg);
    const int var  = blockIdx.y;
    const int row0 = blockIdx.x * RPB;
    const int tid  = threadIdx.x;
    const int lane = tid & 31, wid = tid >> 5;

    const float L2E = 1.4426950408889634f;
    const float c1 = L2E / eps;
    const float c0 = -c1;

    const __half* Gbase = args.G[var];
#pragma unroll
    for (int r = 0; r < RPB; ++r) {
        const __half* Gr = Gbase + (size_t)(row0 + r) * NPTS;
#pragma unroll
        for (int q = 0; q < 4; ++q) {
            int idx = q * 256 + tid;
            cp_async16(smg_u + r * 16384 + idx * 16, Gr + idx * 8);
        }
    }
    asm volatile("cp.async.commit_group;" ::: "memory");

    const float* pot = args.pot[var];
    float pp[32];
#pragma unroll
    for (int it = 0; it < 4; ++it) {
        int idx = it * 256 + tid;
        float4 a = ((const float4*)pot)[2 * idx];
        float4 b = ((const float4*)pot)[2 * idx + 1];
        pp[8 * it + 0] = fmaf(a.x, c1, c0); pp[8 * it + 1] = fmaf(a.y, c1, c0);
        pp[8 * it + 2] = fmaf(a.z, c1, c0); pp[8 * it + 3] = fmaf(a.w, c1, c0);
        pp[8 * it + 4] = fmaf(b.x, c1, c0); pp[8 * it + 5] = fmaf(b.y, c1, c0);
        pp[8 * it + 6] = fmaf(b.z, c1, c0); pp[8 * it + 7] = fmaf(b.w, c1, c0);
    }
    __half2 pph2[16];
#pragma unroll
    for (int j = 0; j < 16; ++j)
        pph2[j] = __floats2half2_rn(pp[2 * j], pp[2 * j + 1]);
    const __half2 c1h2 = __floats2half2_rn(c1, c1);

    asm volatile("cp.async.wait_group 0;" ::: "memory");

    __shared__ float sA[RPB][8];
    __shared__ float sS[RPB][8];

    float wtm[RPB];
#pragma unroll
    for (int r = 0; r < RPB; ++r) {
        __half2 mh = __floats2half2_rn(-60000.0f, -60000.0f);
#pragma unroll
        for (int it = 0; it < 4; ++it) {
            uint4 q = *(const uint4*)(smg + r * 16384 + (it * 256 + tid) * 16);
            const __half2* g2 = (const __half2*)&q;
#pragma unroll
            for (int k = 0; k < 4; ++k)
                mh = __hmax2(mh, __hfma2(g2[k], c1h2, pph2[it * 4 + k]));
        }
        float2 mf = __half22float2(mh);
        float tm = fmaxf(mf.x, mf.y);
#pragma unroll
        for (int off = 16; off > 0; off >>= 1)
            tm = fmaxf(tm, __shfl_xor_sync(0xffffffffu, tm, off));
        wtm[r] = tm;
        if (lane == 0) sA[r][wid] = tm;
    }
    __syncthreads();
    float M[RPB];
#pragma unroll
    for (int r = 0; r < RPB; ++r) {
        float m = sA[r][0];
#pragma unroll
        for (int i = 1; i < 8; ++i) m = fmaxf(m, sA[r][i]);
        M[r] = m;
    }

#pragma unroll
    for (int r = 0; r < RPB; ++r) {
        float s = 0.0f;
        if (wtm[r] >= M[r] - 36.0f) {
            float Mr = M[r];
            float s0 = 0.f, s1 = 0.f, s2 = 0.f, s3 = 0.f;
#pragma unroll
            for (int it = 0; it < 4; ++it) {
                uint4 q = *(const uint4*)(smg + r * 16384 + (it * 256 + tid) * 16);
                float2 g0 = __half22float2(*(const __half2*)&q.x);
                float2 g1 = __half22float2(*(const __half2*)&q.y);
                float2 g2 = __half22float2(*(const __half2*)&q.z);
                float2 g3 = __half22float2(*(const __half2*)&q.w);
                s0 += ex2f_fast(fmaf(g0.x, c1, pp[8 * it + 0]) - Mr);
                s1 += ex2f_fast(fmaf(g0.y, c1, pp[8 * it + 1]) - Mr);
                s2 += ex2f_fast(fmaf(g1.x, c1, pp[8 * it + 2]) - Mr);
                s3 += ex2f_fast(fmaf(g1.y, c1, pp[8 * it + 3]) - Mr);
                s0 += ex2f_fast(fmaf(g2.x, c1, pp[8 * it + 4]) - Mr);
                s1 += ex2f_fast(fmaf(g2.y, c1, pp[8 * it + 5]) - Mr);
                s2 += ex2f_fast(fmaf(g3.x, c1, pp[8 * it + 6]) - Mr);
                s3 += ex2f_fast(fmaf(g3.y, c1, pp[8 * it + 7]) - Mr);
            }
            s = (s0 + s1) + (s2 + s3);
        }
#pragma unroll
        for (int off = 16; off > 0; off >>= 1)
            s += __shfl_xor_sync(0xffffffffu, s, off);
        if (lane == 0) sS[r][wid] = s;
    }
    __syncthreads();

    if (tid < RPB) {
        int r = tid;
        float S = ((sS[r][0] + sS[r][1]) + (sS[r][2] + sS[r][3]))
                + ((sS[r][4] + sS[r][5]) + (sS[r][6] + sS[r][7]));
        const float LOGW = -9.010913347279288f;   // -log(8192)
        const float LN2  = 0.6931471805599453f;
        float lse = (M[r] + log2f(S)) * LN2;
        float res = -eps * (LOGW + lse);
        if (args.avg[var]) res = 0.5f * (args.oldpot[var][row0 + r] + res);
        args.out[var][row0 + r] = res;
    }
}

// ---------------- final reduction ----------------
__global__ void final_reduce(float* __restrict__ out) {
    __shared__ float sh[1024];
    int t = threadIdx.x;
    float s = 0.0f;
    for (int i = t; i < NPTS; i += 1024)
        s += (d_ffin[i] - d_xfin[i]) + (d_gfin[i] - d_yfin[i]);
    sh[t] = s;
    __syncthreads();
    for (int off = 512; off > 0; off >>= 1) {
        if (t < off) sh[t] += sh[t + off];
        __syncthreads();
    }
    if (t == 0) out[0] = sh[0] / (float)NPTS;
}

// ---------------- host ----------------
static void* symaddr(const void* sym) {
    void* p = nullptr;
    cudaGetSymbolAddress(&p, sym);
    return p;
}

extern "C" void kernel_launch(void* const* d_in, const int* in_sizes, int n_in,
                              void* d_out, int out_size) {
    const float* x1 = (const float*)d_in[0];
    const float* x2 = (const float*)d_in[1];
    const float* w  = (const float*)d_in[2];

    __half* an  = (__half*)symaddr(d_anh);
    __half* bn  = (__half*)symaddr(d_bnh);
    __half* Gxy = (__half*)symaddr(d_Gxy);
    __half* Gyx = (__half*)symaddr(d_Gyx);
    __half* Gxx = (__half*)symaddr(d_Gxx);
    __half* Gyy = (__half*)symaddr(d_Gyy);
    float* fb  = (float*)symaddr(d_f);
    float* gb  = (float*)symaddr(d_g);
    float* xb  = (float*)symaddr(d_fxx);
    float* yb  = (float*)symaddr(d_gyy);
    float* ffin = (float*)symaddr(d_ffin);
    float* gfin = (float*)symaddr(d_gfin);
    float* xfin = (float*)symaddr(d_xfin);
    float* yfin = (float*)symaddr(d_yfin);

    cudaFuncSetAttribute(gemm_mma, cudaFuncAttributeMaxDynamicSharedMemorySize, GEMM_SMEM);
    cudaFuncSetAttribute(softmin4, cudaFuncAttributeMaxDynamicSharedMemorySize, SM_SOFTMIN);

    wprep_kernel<<<1, DIM>>>(w);
    rownorm_kernel<<<2 * NPTS, DIM>>>(x1, x2);
    zero_kernel<<<NPTS / 256, 256>>>();

    {
        GArgs ga;
        ga.A[0] = an; ga.B[0] = bn; ga.C[0] = Gxy; ga.CT[0] = Gyx; ga.sym[0] = 0;
        ga.A[1] = an; ga.B[1] = an; ga.C[1] = Gxx; ga.CT[1] = Gxx; ga.sym[1] = 1;
        ga.A[2] = bn; ga.B[2] = bn; ga.C[2] = Gyy; ga.CT[2] = Gyy; ga.sym[2] = 1;
        gemm_mma<<<dim3(NPTS / 128, NPTS / 128, 3), 256, GEMM_SMEM>>>(ga);
    }

    const float eps_list[10] = {4.0f, 1.0f, 0.25f, 0.0625f, 0.015625f,
                                0.00390625f, 0.0025f, 0.0025f, 0.0025f, 0.0025f};
    dim3 sgrid(NPTS / RPB, 4);
    int cur = 0;
    for (int i = 0; i < 10; ++i) {
        float eps = eps_list[i];
        int nxt = 1 - cur;
        SMArgs a;
        a.G[0] = Gxx;  a.pot[0] = xb + cur * NPTS; a.oldpot[0] = xb + cur * NPTS; a.out[0] = xb + nxt * NPTS; a.avg[0] = 1;
        a.G[1] = Gyy;  a.pot[1] = yb + cur * NPTS; a.oldpot[1] = yb + cur * NPTS; a.out[1] = yb + nxt * NPTS; a.avg[1] = 1;
        a.G[2] = Gxy;  a.pot[2] = gb + cur * NPTS; a.oldpot[2] = nullptr;         a.out[2] = fb + nxt * NPTS; a.avg[2] = 0;
        a.G[3] = Gyx;  a.pot[3] = fb + cur * NPTS; a.oldpot[3] = nullptr;         a.out[3] = gb + nxt * NPTS; a.avg[3] = 0;
        softmin4<<<sgrid, 256, SM_SOFTMIN>>>(a, eps);
        cur = nxt;
    }

    const float epsF = 0.0025f;
    {
        SMArgs a;
        a.G[0] = Gxy; a.pot[0] = gb + cur * NPTS; a.oldpot[0] = nullptr; a.out[0] = ffin; a.avg[0] = 0;
        a.G[1] = Gyx; a.pot[1] = fb + cur * NPTS; a.oldpot[1] = nullptr; a.out[1] = gfin; a.avg[1] = 0;
        a.G[2] = Gxx; a.pot[2] = xb + cur * NPTS; a.oldpot[2] = nullptr; a.out[2] = xfin; a.avg[2] = 0;
        a.G[3] = Gyy; a.pot[3] = yb + cur * NPTS; a.oldpot[3] = nullptr; a.out[3] = yfin; a.avg[3] = 0;
        softmin4<<<sgrid, 256, SM_SOFTMIN>>>(a, epsF);
    }

    final_reduce<<<1, 1024>>>((float*)d_out);
}